// round 1
// baseline (speedup 1.0000x reference)
#include <cuda_runtime.h>
#include <cstdint>
#include <cstddef>

#define TOK    12288
#define DMODEL 1024
#define QKVN   6144
#define ATTN   2048

// Scratch (static device globals: allocation-free per harness rules)
static __device__ float g_QKV[(size_t)TOK * QKVN];  // [t][mat*1024 + h*64 + d], mat: Q,K,V,Qmv,Kmv,Vmv
static __device__ float g_ATT[(size_t)TOK * ATTN];  // [t][0..1023]=main attn out, [1024..2047]=mv combined

struct Ptr6 { const float* p[6]; };

// ---------------------------------------------------------------------------
// GEMM1: C[t, n] = sum_d x[t,d] * W_{n/1024}[n%1024, d]   (NT GEMM, fp32 SIMT)
// 128x128 block tile, BK=16, 256 threads, 8x8 micro-tile.
// ---------------------------------------------------------------------------
__global__ __launch_bounds__(256) void gemm_qkv(const float* __restrict__ A, Ptr6 B) {
  __shared__ __align__(16) float As[16][128];
  __shared__ __align__(16) float Bs[16][128];
  const int tid = threadIdx.x;
  const int m0 = blockIdx.y * 128;
  const int n0 = blockIdx.x * 128;
  const float* __restrict__ Bmat = B.p[n0 >> 10];
  const int br0 = n0 & 1023;
  const int tm = (tid >> 4) * 8;
  const int tn = (tid & 15) * 8;
  float acc[8][8];
#pragma unroll
  for (int i = 0; i < 8; i++)
#pragma unroll
    for (int j = 0; j < 8; j++) acc[i][j] = 0.f;

  for (int k0 = 0; k0 < DMODEL; k0 += 16) {
#pragma unroll
    for (int i = 0; i < 2; i++) {
      int idx = tid + i * 256;        // 0..511
      int r = idx >> 2;               // 0..127
      int c4 = (idx & 3) * 4;         // 0,4,8,12
      float4 va = *(const float4*)&A[(size_t)(m0 + r) * DMODEL + k0 + c4];
      As[c4 + 0][r] = va.x; As[c4 + 1][r] = va.y;
      As[c4 + 2][r] = va.z; As[c4 + 3][r] = va.w;
      float4 vb = *(const float4*)&Bmat[(size_t)(br0 + r) * DMODEL + k0 + c4];
      Bs[c4 + 0][r] = vb.x; Bs[c4 + 1][r] = vb.y;
      Bs[c4 + 2][r] = vb.z; Bs[c4 + 3][r] = vb.w;
    }
    __syncthreads();
#pragma unroll
    for (int kk = 0; kk < 16; kk++) {
      float4 a0 = *(const float4*)&As[kk][tm];
      float4 a1 = *(const float4*)&As[kk][tm + 4];
      float4 b0 = *(const float4*)&Bs[kk][tn];
      float4 b1 = *(const float4*)&Bs[kk][tn + 4];
      float a[8] = {a0.x, a0.y, a0.z, a0.w, a1.x, a1.y, a1.z, a1.w};
      float b[8] = {b0.x, b0.y, b0.z, b0.w, b1.x, b1.y, b1.z, b1.w};
#pragma unroll
      for (int i = 0; i < 8; i++)
#pragma unroll
        for (int j = 0; j < 8; j++) acc[i][j] += a[i] * b[j];
    }
    __syncthreads();
  }
#pragma unroll
  for (int i = 0; i < 8; i++) {
    float* Crow = &g_QKV[(size_t)(m0 + tm + i) * QKVN + n0 + tn];
    *(float4*)&Crow[0] = make_float4(acc[i][0], acc[i][1], acc[i][2], acc[i][3]);
    *(float4*)&Crow[4] = make_float4(acc[i][4], acc[i][5], acc[i][6], acc[i][7]);
  }
}

// ---------------------------------------------------------------------------
// Main attention: grid (32 qtiles, 192 bh). Q_TILE=32, KT=64, online softmax.
// Thread (q = tid/8, l8 = tid%8): owns 8 out dims d = l8*8+j and 8 keys/tile.
// ---------------------------------------------------------------------------
__global__ __launch_bounds__(256) void attn_main() {
  __shared__ __align__(16) float Qs[32][68];
  __shared__ __align__(16) float KVs[64][68];
  __shared__ __align__(16) float Ps[32][68];
  const int tid = threadIdx.x;
  const int qt = blockIdx.x;              // 0..31
  const int b  = blockIdx.y >> 4;
  const int h  = blockIdx.y & 15;
  const int tb = b << 10;
  const int colQ = h * 64;
  const int colK = 1024 + h * 64;
  const int colV = 2048 + h * 64;

#pragma unroll
  for (int i = 0; i < 2; i++) {
    int id = tid + i * 256;               // 0..511
    int r = id >> 4, c4 = (id & 15) * 4;
    *(float4*)&Qs[r][c4] =
        *(const float4*)&g_QKV[(size_t)(tb + qt * 32 + r) * QKVN + colQ + c4];
  }
  const int q = tid >> 3;
  const int l8 = tid & 7;
  float m = -1e30f, lsum = 0.f;
  float o[8];
#pragma unroll
  for (int j = 0; j < 8; j++) o[j] = 0.f;

  for (int kt = 0; kt < 16; kt++) {
    __syncthreads();                      // protect KVs (prev V) before overwrite
#pragma unroll
    for (int i = 0; i < 4; i++) {
      int id = tid + i * 256;             // 0..1023
      int r = id >> 4, c4 = (id & 15) * 4;
      *(float4*)&KVs[r][c4] =
          *(const float4*)&g_QKV[(size_t)(tb + kt * 64 + r) * QKVN + colK + c4];
    }
    __syncthreads();
    float s[8];
#pragma unroll
    for (int j = 0; j < 8; j++) s[j] = 0.f;
#pragma unroll
    for (int d0 = 0; d0 < 64; d0 += 4) {
      float4 qv = *(const float4*)&Qs[q][d0];
#pragma unroll
      for (int j = 0; j < 8; j++) {
        float4 kv = *(const float4*)&KVs[j * 8 + l8][d0];
        s[j] += qv.x * kv.x + qv.y * kv.y + qv.z * kv.z + qv.w * kv.w;
      }
    }
    float tmax = -1e30f;
#pragma unroll
    for (int j = 0; j < 8; j++) { s[j] *= 0.125f; tmax = fmaxf(tmax, s[j]); }
#pragma unroll
    for (int off = 1; off < 8; off <<= 1)
      tmax = fmaxf(tmax, __shfl_xor_sync(0xffffffffu, tmax, off));
    float mnew = fmaxf(m, tmax);
    float corr = __expf(m - mnew);
    float psum = 0.f;
#pragma unroll
    for (int j = 0; j < 8; j++) {
      float p = __expf(s[j] - mnew);
      Ps[q][j * 8 + l8] = p;
      psum += p;
    }
#pragma unroll
    for (int off = 1; off < 8; off <<= 1)
      psum += __shfl_xor_sync(0xffffffffu, psum, off);
    lsum = lsum * corr + psum;
    m = mnew;
#pragma unroll
    for (int j = 0; j < 8; j++) o[j] *= corr;
    __syncthreads();                      // Ps written, KVs free
#pragma unroll
    for (int i = 0; i < 4; i++) {
      int id = tid + i * 256;
      int r = id >> 4, c4 = (id & 15) * 4;
      *(float4*)&KVs[r][c4] =
          *(const float4*)&g_QKV[(size_t)(tb + kt * 64 + r) * QKVN + colV + c4];
    }
    __syncthreads();
#pragma unroll
    for (int k = 0; k < 64; k++) {
      float p = Ps[q][k];
      float4 v0 = *(const float4*)&KVs[k][l8 * 8];
      float4 v1 = *(const float4*)&KVs[k][l8 * 8 + 4];
      o[0] += p * v0.x; o[1] += p * v0.y; o[2] += p * v0.z; o[3] += p * v0.w;
      o[4] += p * v1.x; o[5] += p * v1.y; o[6] += p * v1.z; o[7] += p * v1.w;
    }
  }
  float inv = 1.f / lsum;
  const int t = tb + qt * 32 + q;
  float* dst = &g_ATT[(size_t)t * ATTN + h * 64 + l8 * 8];
  *(float4*)&dst[0] = make_float4(o[0] * inv, o[1] * inv, o[2] * inv, o[3] * inv);
  *(float4*)&dst[4] = make_float4(o[4] * inv, o[5] * inv, o[6] * inv, o[7] * inv);
}

// ---------------------------------------------------------------------------
// Row/Col view attention. grid (4 qtiles, 1024 groups). Seq = 128 (2 key tiles).
// Row: group (bb, ih, h); j = nv*32+iw.   Col: group (bb, iw, h); j = c*32+ih.
// ---------------------------------------------------------------------------
__device__ __forceinline__ int mv_token(int bb, int j, int ij, int is_col) {
  int c = j >> 5, pos = j & 31;
  int nv = is_col ? ((c < 3) ? 2 * c : 5) : c;      // COL_IDX = {0,2,4,5}
  int s  = is_col ? (pos * 32 + ij) : (ij * 32 + pos);
  return (bb * 6 + nv) * 1024 + s;
}

template <int IS_COL>
__global__ __launch_bounds__(256) void attn_mv() {
  __shared__ __align__(16) float Qs[32][68];
  __shared__ __align__(16) float KVs[64][68];
  __shared__ __align__(16) float Ps[32][68];
  const int tid = threadIdx.x;
  const int qt = blockIdx.x;                 // 0..3 (nv for row / c for col)
  const int gy = blockIdx.y;                 // (bb*32 + ij)*16 + h
  const int h  = gy & 15;
  const int ij = (gy >> 4) & 31;             // ih (row) / iw (col)
  const int bb = gy >> 9;
  const int colQ = 3072 + h * 64;
  const int colK = 4096 + h * 64;
  const int colV = 5120 + h * 64;

#pragma unroll
  for (int i = 0; i < 2; i++) {
    int id = tid + i * 256;
    int r = id >> 4, c4 = (id & 15) * 4;
    int t = mv_token(bb, qt * 32 + r, ij, IS_COL);
    *(float4*)&Qs[r][c4] = *(const float4*)&g_QKV[(size_t)t * QKVN + colQ + c4];
  }
  const int q = tid >> 3;
  const int l8 = tid & 7;
  float m = -1e30f, lsum = 0.f;
  float o[8];
#pragma unroll
  for (int j = 0; j < 8; j++) o[j] = 0.f;

  for (int kt = 0; kt < 2; kt++) {
    __syncthreads();
#pragma unroll
    for (int i = 0; i < 4; i++) {
      int id = tid + i * 256;
      int r = id >> 4, c4 = (id & 15) * 4;
      int t = mv_token(bb, kt * 64 + r, ij, IS_COL);
      *(float4*)&KVs[r][c4] = *(const float4*)&g_QKV[(size_t)t * QKVN + colK + c4];
    }
    __syncthreads();
    float s[8];
#pragma unroll
    for (int j = 0; j < 8; j++) s[j] = 0.f;
#pragma unroll
    for (int d0 = 0; d0 < 64; d0 += 4) {
      float4 qv = *(const float4*)&Qs[q][d0];
#pragma unroll
      for (int j = 0; j < 8; j++) {
        float4 kv = *(const float4*)&KVs[j * 8 + l8][d0];
        s[j] += qv.x * kv.x + qv.y * kv.y + qv.z * kv.z + qv.w * kv.w;
      }
    }
    float tmax = -1e30f;
#pragma unroll
    for (int j = 0; j < 8; j++) { s[j] *= 0.125f; tmax = fmaxf(tmax, s[j]); }
#pragma unroll
    for (int off = 1; off < 8; off <<= 1)
      tmax = fmaxf(tmax, __shfl_xor_sync(0xffffffffu, tmax, off));
    float mnew = fmaxf(m, tmax);
    float corr = __expf(m - mnew);
    float psum = 0.f;
#pragma unroll
    for (int j = 0; j < 8; j++) {
      float p = __expf(s[j] - mnew);
      Ps[q][j * 8 + l8] = p;
      psum += p;
    }
#pragma unroll
    for (int off = 1; off < 8; off <<= 1)
      psum += __shfl_xor_sync(0xffffffffu, psum, off);
    lsum = lsum * corr + psum;
    m = mnew;
#pragma unroll
    for (int j = 0; j < 8; j++) o[j] *= corr;
    __syncthreads();
#pragma unroll
    for (int i = 0; i < 4; i++) {
      int id = tid + i * 256;
      int r = id >> 4, c4 = (id & 15) * 4;
      int t = mv_token(bb, kt * 64 + r, ij, IS_COL);
      *(float4*)&KVs[r][c4] = *(const float4*)&g_QKV[(size_t)t * QKVN + colV + c4];
    }
    __syncthreads();
#pragma unroll
    for (int k = 0; k < 64; k++) {
      float p = Ps[q][k];
      float4 v0 = *(const float4*)&KVs[k][l8 * 8];
      float4 v1 = *(const float4*)&KVs[k][l8 * 8 + 4];
      o[0] += p * v0.x; o[1] += p * v0.y; o[2] += p * v0.z; o[3] += p * v0.w;
      o[4] += p * v1.x; o[5] += p * v1.y; o[6] += p * v1.z; o[7] += p * v1.w;
    }
  }
  float inv = 1.f / lsum;
  const int t = mv_token(bb, qt * 32 + q, ij, IS_COL);
  float* dst = &g_ATT[(size_t)t * ATTN + 1024 + h * 64 + l8 * 8];
  float4 r0 = make_float4(o[0] * inv, o[1] * inv, o[2] * inv, o[3] * inv);
  float4 r1 = make_float4(o[4] * inv, o[5] * inv, o[6] * inv, o[7] * inv);
  if (IS_COL) {
    // col runs first: always WRITE, weight 0.5 for c in {0,1}, else 1.0
    float w = (qt < 2) ? 0.5f : 1.0f;
    *(float4*)&dst[0] = make_float4(w * r0.x, w * r0.y, w * r0.z, w * r0.w);
    *(float4*)&dst[4] = make_float4(w * r1.x, w * r1.y, w * r1.z, w * r1.w);
  } else {
    // row runs second: ADD 0.5x for nv in {0,2}, WRITE for nv in {1,3}
    if (qt == 0 || qt == 2) {
      float4 c0 = *(const float4*)&dst[0];
      float4 c1 = *(const float4*)&dst[4];
      c0.x += 0.5f * r0.x; c0.y += 0.5f * r0.y; c0.z += 0.5f * r0.z; c0.w += 0.5f * r0.w;
      c1.x += 0.5f * r1.x; c1.y += 0.5f * r1.y; c1.z += 0.5f * r1.z; c1.w += 0.5f * r1.w;
      *(float4*)&dst[0] = c0;
      *(float4*)&dst[4] = c1;
    } else {
      *(float4*)&dst[0] = r0;
      *(float4*)&dst[4] = r1;
    }
  }
}

// ---------------------------------------------------------------------------
// GEMM2: out[t,n] = sum_{k<1024} ATT[t,k]*Wo[n,k] + sum_{k>=1024} ATT[t,k]*Wom[n,k-1024]
//                   + bo[n] + bom[n] + x[t,n]
// ---------------------------------------------------------------------------
__global__ __launch_bounds__(256) void gemm_out(
    const float* __restrict__ Wo, const float* __restrict__ Wom,
    const float* __restrict__ bo, const float* __restrict__ bom,
    const float* __restrict__ X, float* __restrict__ Out) {
  __shared__ __align__(16) float As[16][128];
  __shared__ __align__(16) float Bs[16][128];
  const int tid = threadIdx.x;
  const int m0 = blockIdx.y * 128;
  const int n0 = blockIdx.x * 128;
  const int tm = (tid >> 4) * 8;
  const int tn = (tid & 15) * 8;
  float acc[8][8];
#pragma unroll
  for (int i = 0; i < 8; i++)
#pragma unroll
    for (int j = 0; j < 8; j++) acc[i][j] = 0.f;

  for (int k0 = 0; k0 < ATTN; k0 += 16) {
    const float* __restrict__ Bmat = (k0 < 1024) ? Wo : Wom;
    const int kc = k0 & 1023;
#pragma unroll
    for (int i = 0; i < 2; i++) {
      int idx = tid + i * 256;
      int r = idx >> 2;
      int c4 = (idx & 3) * 4;
      float4 va = *(const float4*)&g_ATT[(size_t)(m0 + r) * ATTN + k0 + c4];
      As[c4 + 0][r] = va.x; As[c4 + 1][r] = va.y;
      As[c4 + 2][r] = va.z; As[c4 + 3][r] = va.w;
      float4 vb = *(const float4*)&Bmat[(size_t)(n0 + r) * DMODEL + kc + c4];
      Bs[c4 + 0][r] = vb.x; Bs[c4 + 1][r] = vb.y;
      Bs[c4 + 2][r] = vb.z; Bs[c4 + 3][r] = vb.w;
    }
    __syncthreads();
#pragma unroll
    for (int kk = 0; kk < 16; kk++) {
      float4 a0 = *(const float4*)&As[kk][tm];
      float4 a1 = *(const float4*)&As[kk][tm + 4];
      float4 b0 = *(const float4*)&Bs[kk][tn];
      float4 b1 = *(const float4*)&Bs[kk][tn + 4];
      float a[8] = {a0.x, a0.y, a0.z, a0.w, a1.x, a1.y, a1.z, a1.w};
      float b[8] = {b0.x, b0.y, b0.z, b0.w, b1.x, b1.y, b1.z, b1.w};
#pragma unroll
      for (int i = 0; i < 8; i++)
#pragma unroll
        for (int j = 0; j < 8; j++) acc[i][j] += a[i] * b[j];
    }
    __syncthreads();
  }
#pragma unroll
  for (int i = 0; i < 8; i++) {
    int mrow = m0 + tm + i;
    const float* xr = &X[(size_t)mrow * DMODEL + n0 + tn];
    float* orow = &Out[(size_t)mrow * DMODEL + n0 + tn];
#pragma unroll
    for (int j = 0; j < 8; j++) {
      int n = n0 + tn + j;
      orow[j] = acc[i][j] + bo[n] + bom[n] + xr[j];
    }
  }
}

// ---------------------------------------------------------------------------
extern "C" void kernel_launch(void* const* d_in, const int* in_sizes, int n_in,
                              void* d_out, int out_size) {
  (void)in_sizes; (void)n_in; (void)out_size;
  const float* x   = (const float*)d_in[0];
  const float* Wq  = (const float*)d_in[1];
  const float* Wk  = (const float*)d_in[2];
  const float* Wv  = (const float*)d_in[3];
  const float* Wo  = (const float*)d_in[4];
  const float* bo  = (const float*)d_in[5];
  const float* Wqm = (const float*)d_in[6];
  const float* Wkm = (const float*)d_in[7];
  const float* Wvm = (const float*)d_in[8];
  const float* Wom = (const float*)d_in[9];
  const float* bom = (const float*)d_in[10];
  float* out = (float*)d_out;

  Ptr6 B1;
  B1.p[0] = Wq;  B1.p[1] = Wk;  B1.p[2] = Wv;
  B1.p[3] = Wqm; B1.p[4] = Wkm; B1.p[5] = Wvm;

  gemm_qkv<<<dim3(QKVN / 128, TOK / 128), 256>>>(x, B1);
  attn_main<<<dim3(32, 192), 256>>>();
  attn_mv<1><<<dim3(4, 1024), 256>>>();   // col views: write
  attn_mv<0><<<dim3(4, 1024), 256>>>();   // row views: add/write (after col)
  gemm_out<<<dim3(DMODEL / 128, TOK / 128), 256>>>(Wo, Wom, bo, bom, x, out);
}

// round 2
// speedup vs baseline: 1.4499x; 1.4499x over previous
#include <cuda_runtime.h>
#include <cstdint>
#include <cstddef>

#define TOK    12288
#define DMODEL 1024
#define QKVN   6144
#define ATTN   2048

// Scratch (static device globals: allocation-free per harness rules)
static __device__ float g_QKV[(size_t)TOK * QKVN];  // [t][mat*1024 + h*64 + d], mat: Q,K,V,Qmv,Kmv,Vmv
static __device__ float g_ATT[(size_t)TOK * ATTN];  // [t][0..1023]=main attn out, [1024..2047]=mv combined

struct Ptr6 { const float* p[6]; };

// ---------------------------------------------------------------------------
// tf32 helpers
// ---------------------------------------------------------------------------
__device__ __forceinline__ unsigned f2tf(float f) {
  unsigned u;
  asm("cvt.rna.tf32.f32 %0, %1;" : "=r"(u) : "f"(f));
  return u;
}

__device__ __forceinline__ void mma_tf32(float* d, const unsigned* a,
                                         const unsigned* b, const float* c) {
  asm volatile(
      "mma.sync.aligned.m16n8k8.row.col.f32.tf32.tf32.f32 "
      "{%0,%1,%2,%3}, {%4,%5,%6,%7}, {%8,%9}, {%10,%11,%12,%13};\n"
      : "=f"(d[0]), "=f"(d[1]), "=f"(d[2]), "=f"(d[3])
      : "r"(a[0]), "r"(a[1]), "r"(a[2]), "r"(a[3]), "r"(b[0]), "r"(b[1]),
        "f"(c[0]), "f"(c[1]), "f"(c[2]), "f"(c[3]));
}

// Convert float4 -> tf32 bits and store as one 16B STS.
__device__ __forceinline__ void sts_tf4(unsigned* p, float4 v) {
  uint4 u;
  u.x = f2tf(v.x); u.y = f2tf(v.y); u.z = f2tf(v.z); u.w = f2tf(v.w);
  *(uint4*)p = u;
}

// ---------------------------------------------------------------------------
// GEMM1 (tensor core, tf32): C[t,n] = sum_d x[t,d] * W_{n/1024}[n%1024, d]
// 128x128 tile, BK=16, 256 threads (8 warps, 64x32 warp tiles), double buffer.
// ---------------------------------------------------------------------------
#define GPAD 20
__global__ __launch_bounds__(256) void gemm_qkv(const float* __restrict__ A, Ptr6 B) {
  __shared__ __align__(16) unsigned As[2][128][GPAD];
  __shared__ __align__(16) unsigned Bs[2][128][GPAD];
  const int tid = threadIdx.x;
  const int m0 = blockIdx.y * 128;
  const int n0 = blockIdx.x * 128;
  const float* __restrict__ Bmat = B.p[n0 >> 10];
  const int br0 = n0 & 1023;

  const int lane = tid & 31, wid = tid >> 5;
  const int wm = (wid & 1) * 64, wn = (wid >> 1) * 32;
  const int g = lane >> 2, tg = lane & 3;

  // staging indices: thread covers idx = tid and tid+256 of 512 float4 slots
  const int r0 = tid >> 2, c40 = (tid & 3) << 2;
  const int r1 = (tid + 256) >> 2, c41 = ((tid + 256) & 3) << 2;

  float acc[4][4][4];
#pragma unroll
  for (int mi = 0; mi < 4; mi++)
#pragma unroll
    for (int ni = 0; ni < 4; ni++)
#pragma unroll
      for (int r = 0; r < 4; r++) acc[mi][ni][r] = 0.f;

  // prologue: load chunk 0
  float4 a0v = *(const float4*)&A[(size_t)(m0 + r0) * DMODEL + c40];
  float4 a1v = *(const float4*)&A[(size_t)(m0 + r1) * DMODEL + c41];
  float4 b0v = *(const float4*)&Bmat[(size_t)(br0 + r0) * DMODEL + c40];
  float4 b1v = *(const float4*)&Bmat[(size_t)(br0 + r1) * DMODEL + c41];
  sts_tf4(&As[0][r0][c40], a0v); sts_tf4(&As[0][r1][c41], a1v);
  sts_tf4(&Bs[0][r0][c40], b0v); sts_tf4(&Bs[0][r1][c41], b1v);
  __syncthreads();

  const int NC = DMODEL / 16;
  for (int kc = 0; kc < NC; kc++) {
    int buf = kc & 1;
    if (kc + 1 < NC) {
      int k0 = (kc + 1) * 16;
      a0v = *(const float4*)&A[(size_t)(m0 + r0) * DMODEL + k0 + c40];
      a1v = *(const float4*)&A[(size_t)(m0 + r1) * DMODEL + k0 + c41];
      b0v = *(const float4*)&Bmat[(size_t)(br0 + r0) * DMODEL + k0 + c40];
      b1v = *(const float4*)&Bmat[(size_t)(br0 + r1) * DMODEL + k0 + c41];
    }
#pragma unroll
    for (int kk = 0; kk < 16; kk += 8) {
      unsigned a[4][4], b[4][2];
#pragma unroll
      for (int mi = 0; mi < 4; mi++) {
        int row = wm + mi * 16;
        a[mi][0] = As[buf][row + g][kk + tg];
        a[mi][1] = As[buf][row + g + 8][kk + tg];
        a[mi][2] = As[buf][row + g][kk + tg + 4];
        a[mi][3] = As[buf][row + g + 8][kk + tg + 4];
      }
#pragma unroll
      for (int ni = 0; ni < 4; ni++) {
        int col = wn + ni * 8;
        b[ni][0] = Bs[buf][col + g][kk + tg];
        b[ni][1] = Bs[buf][col + g][kk + tg + 4];
      }
#pragma unroll
      for (int mi = 0; mi < 4; mi++)
#pragma unroll
        for (int ni = 0; ni < 4; ni++)
          mma_tf32(acc[mi][ni], a[mi], b[ni], acc[mi][ni]);
    }
    if (kc + 1 < NC) {
      int nb = (kc + 1) & 1;
      sts_tf4(&As[nb][r0][c40], a0v); sts_tf4(&As[nb][r1][c41], a1v);
      sts_tf4(&Bs[nb][r0][c40], b0v); sts_tf4(&Bs[nb][r1][c41], b1v);
      __syncthreads();
    }
  }

  // epilogue: acc layout c0:(g, 2tg) c1:(g, 2tg+1) c2:(g+8, 2tg) c3:(g+8, 2tg+1)
#pragma unroll
  for (int mi = 0; mi < 4; mi++) {
#pragma unroll
    for (int ni = 0; ni < 4; ni++) {
      int row = m0 + wm + mi * 16 + g;
      int col = n0 + wn + ni * 8 + 2 * tg;
      *(float2*)&g_QKV[(size_t)row * QKVN + col] =
          make_float2(acc[mi][ni][0], acc[mi][ni][1]);
      *(float2*)&g_QKV[(size_t)(row + 8) * QKVN + col] =
          make_float2(acc[mi][ni][2], acc[mi][ni][3]);
    }
  }
}

// ---------------------------------------------------------------------------
// GEMM2 (tensor core, tf32):
// out[t,n] = sum_{k<1024} ATT[t,k]*Wo[n,k] + sum_{k>=1024} ATT[t,k]*Wom[n,k-1024]
//            + bo[n] + bom[n] + x[t,n]
// ---------------------------------------------------------------------------
__global__ __launch_bounds__(256) void gemm_out(
    const float* __restrict__ Wo, const float* __restrict__ Wom,
    const float* __restrict__ bo, const float* __restrict__ bom,
    const float* __restrict__ X, float* __restrict__ Out) {
  __shared__ __align__(16) unsigned As[2][128][GPAD];
  __shared__ __align__(16) unsigned Bs[2][128][GPAD];
  const int tid = threadIdx.x;
  const int m0 = blockIdx.y * 128;
  const int n0 = blockIdx.x * 128;

  const int lane = tid & 31, wid = tid >> 5;
  const int wm = (wid & 1) * 64, wn = (wid >> 1) * 32;
  const int g = lane >> 2, tg = lane & 3;

  const int r0 = tid >> 2, c40 = (tid & 3) << 2;
  const int r1 = (tid + 256) >> 2, c41 = ((tid + 256) & 3) << 2;

  float acc[4][4][4];
#pragma unroll
  for (int mi = 0; mi < 4; mi++)
#pragma unroll
    for (int ni = 0; ni < 4; ni++)
#pragma unroll
      for (int r = 0; r < 4; r++) acc[mi][ni][r] = 0.f;

  float4 a0v = *(const float4*)&g_ATT[(size_t)(m0 + r0) * ATTN + c40];
  float4 a1v = *(const float4*)&g_ATT[(size_t)(m0 + r1) * ATTN + c41];
  float4 b0v = *(const float4*)&Wo[(size_t)(n0 + r0) * DMODEL + c40];
  float4 b1v = *(const float4*)&Wo[(size_t)(n0 + r1) * DMODEL + c41];
  sts_tf4(&As[0][r0][c40], a0v); sts_tf4(&As[0][r1][c41], a1v);
  sts_tf4(&Bs[0][r0][c40], b0v); sts_tf4(&Bs[0][r1][c41], b1v);
  __syncthreads();

  const int NC = ATTN / 16;
  for (int kc = 0; kc < NC; kc++) {
    int buf = kc & 1;
    if (kc + 1 < NC) {
      int k0 = (kc + 1) * 16;
      const float* __restrict__ Bmat = (k0 < 1024) ? Wo : Wom;
      int kcc = k0 & 1023;
      a0v = *(const float4*)&g_ATT[(size_t)(m0 + r0) * ATTN + k0 + c40];
      a1v = *(const float4*)&g_ATT[(size_t)(m0 + r1) * ATTN + k0 + c41];
      b0v = *(const float4*)&Bmat[(size_t)(n0 + r0) * DMODEL + kcc + c40];
      b1v = *(const float4*)&Bmat[(size_t)(n0 + r1) * DMODEL + kcc + c41];
    }
#pragma unroll
    for (int kk = 0; kk < 16; kk += 8) {
      unsigned a[4][4], b[4][2];
#pragma unroll
      for (int mi = 0; mi < 4; mi++) {
        int row = wm + mi * 16;
        a[mi][0] = As[buf][row + g][kk + tg];
        a[mi][1] = As[buf][row + g + 8][kk + tg];
        a[mi][2] = As[buf][row + g][kk + tg + 4];
        a[mi][3] = As[buf][row + g + 8][kk + tg + 4];
      }
#pragma unroll
      for (int ni = 0; ni < 4; ni++) {
        int col = wn + ni * 8;
        b[ni][0] = Bs[buf][col + g][kk + tg];
        b[ni][1] = Bs[buf][col + g][kk + tg + 4];
      }
#pragma unroll
      for (int mi = 0; mi < 4; mi++)
#pragma unroll
        for (int ni = 0; ni < 4; ni++)
          mma_tf32(acc[mi][ni], a[mi], b[ni], acc[mi][ni]);
    }
    if (kc + 1 < NC) {
      int nb = (kc + 1) & 1;
      sts_tf4(&As[nb][r0][c40], a0v); sts_tf4(&As[nb][r1][c41], a1v);
      sts_tf4(&Bs[nb][r0][c40], b0v); sts_tf4(&Bs[nb][r1][c41], b1v);
      __syncthreads();
    }
  }

#pragma unroll
  for (int mi = 0; mi < 4; mi++) {
#pragma unroll
    for (int ni = 0; ni < 4; ni++) {
      int row = m0 + wm + mi * 16 + g;
      int col = n0 + wn + ni * 8 + 2 * tg;
      float bias0 = bo[col] + bom[col];
      float bias1 = bo[col + 1] + bom[col + 1];
      float2 x0 = *(const float2*)&X[(size_t)row * DMODEL + col];
      float2 x1 = *(const float2*)&X[(size_t)(row + 8) * DMODEL + col];
      *(float2*)&Out[(size_t)row * DMODEL + col] =
          make_float2(acc[mi][ni][0] + bias0 + x0.x, acc[mi][ni][1] + bias1 + x0.y);
      *(float2*)&Out[(size_t)(row + 8) * DMODEL + col] =
          make_float2(acc[mi][ni][2] + bias0 + x1.x, acc[mi][ni][3] + bias1 + x1.y);
    }
  }
}

// ---------------------------------------------------------------------------
// Main attention: grid (32 qtiles, 192 bh). Q_TILE=32, KT=64, online softmax.
// ---------------------------------------------------------------------------
__global__ __launch_bounds__(256) void attn_main() {
  __shared__ __align__(16) float Qs[32][68];
  __shared__ __align__(16) float KVs[64][68];
  __shared__ __align__(16) float Ps[32][68];
  const int tid = threadIdx.x;
  const int qt = blockIdx.x;
  const int b  = blockIdx.y >> 4;
  const int h  = blockIdx.y & 15;
  const int tb = b << 10;
  const int colQ = h * 64;
  const int colK = 1024 + h * 64;
  const int colV = 2048 + h * 64;

#pragma unroll
  for (int i = 0; i < 2; i++) {
    int id = tid + i * 256;
    int r = id >> 4, c4 = (id & 15) * 4;
    *(float4*)&Qs[r][c4] =
        *(const float4*)&g_QKV[(size_t)(tb + qt * 32 + r) * QKVN + colQ + c4];
  }
  const int q = tid >> 3;
  const int l8 = tid & 7;
  float m = -1e30f, lsum = 0.f;
  float o[8];
#pragma unroll
  for (int j = 0; j < 8; j++) o[j] = 0.f;

  for (int kt = 0; kt < 16; kt++) {
    __syncthreads();
#pragma unroll
    for (int i = 0; i < 4; i++) {
      int id = tid + i * 256;
      int r = id >> 4, c4 = (id & 15) * 4;
      *(float4*)&KVs[r][c4] =
          *(const float4*)&g_QKV[(size_t)(tb + kt * 64 + r) * QKVN + colK + c4];
    }
    __syncthreads();
    float s[8];
#pragma unroll
    for (int j = 0; j < 8; j++) s[j] = 0.f;
#pragma unroll
    for (int d0 = 0; d0 < 64; d0 += 4) {
      float4 qv = *(const float4*)&Qs[q][d0];
#pragma unroll
      for (int j = 0; j < 8; j++) {
        float4 kv = *(const float4*)&KVs[j * 8 + l8][d0];
        s[j] += qv.x * kv.x + qv.y * kv.y + qv.z * kv.z + qv.w * kv.w;
      }
    }
    float tmax = -1e30f;
#pragma unroll
    for (int j = 0; j < 8; j++) { s[j] *= 0.125f; tmax = fmaxf(tmax, s[j]); }
#pragma unroll
    for (int off = 1; off < 8; off <<= 1)
      tmax = fmaxf(tmax, __shfl_xor_sync(0xffffffffu, tmax, off));
    float mnew = fmaxf(m, tmax);
    float corr = __expf(m - mnew);
    float psum = 0.f;
#pragma unroll
    for (int j = 0; j < 8; j++) {
      float p = __expf(s[j] - mnew);
      Ps[q][j * 8 + l8] = p;
      psum += p;
    }
#pragma unroll
    for (int off = 1; off < 8; off <<= 1)
      psum += __shfl_xor_sync(0xffffffffu, psum, off);
    lsum = lsum * corr + psum;
    m = mnew;
#pragma unroll
    for (int j = 0; j < 8; j++) o[j] *= corr;
    __syncthreads();
#pragma unroll
    for (int i = 0; i < 4; i++) {
      int id = tid + i * 256;
      int r = id >> 4, c4 = (id & 15) * 4;
      *(float4*)&KVs[r][c4] =
          *(const float4*)&g_QKV[(size_t)(tb + kt * 64 + r) * QKVN + colV + c4];
    }
    __syncthreads();
#pragma unroll
    for (int k = 0; k < 64; k++) {
      float p = Ps[q][k];
      float4 v0 = *(const float4*)&KVs[k][l8 * 8];
      float4 v1 = *(const float4*)&KVs[k][l8 * 8 + 4];
      o[0] += p * v0.x; o[1] += p * v0.y; o[2] += p * v0.z; o[3] += p * v0.w;
      o[4] += p * v1.x; o[5] += p * v1.y; o[6] += p * v1.z; o[7] += p * v1.w;
    }
  }
  float inv = 1.f / lsum;
  const int t = tb + qt * 32 + q;
  float* dst = &g_ATT[(size_t)t * ATTN + h * 64 + l8 * 8];
  *(float4*)&dst[0] = make_float4(o[0] * inv, o[1] * inv, o[2] * inv, o[3] * inv);
  *(float4*)&dst[4] = make_float4(o[4] * inv, o[5] * inv, o[6] * inv, o[7] * inv);
}

// ---------------------------------------------------------------------------
// Row/Col view attention. grid (4 qtiles, 1024 groups). Seq = 128 (2 key tiles).
// ---------------------------------------------------------------------------
__device__ __forceinline__ int mv_token(int bb, int j, int ij, int is_col) {
  int c = j >> 5, pos = j & 31;
  int nv = is_col ? ((c < 3) ? 2 * c : 5) : c;  // COL_IDX = {0,2,4,5}
  int s  = is_col ? (pos * 32 + ij) : (ij * 32 + pos);
  return (bb * 6 + nv) * 1024 + s;
}

template <int IS_COL>
__global__ __launch_bounds__(256) void attn_mv() {
  __shared__ __align__(16) float Qs[32][68];
  __shared__ __align__(16) float KVs[64][68];
  __shared__ __align__(16) float Ps[32][68];
  const int tid = threadIdx.x;
  const int qt = blockIdx.x;
  const int gy = blockIdx.y;
  const int h  = gy & 15;
  const int ij = (gy >> 4) & 31;
  const int bb = gy >> 9;
  const int colQ = 3072 + h * 64;
  const int colK = 4096 + h * 64;
  const int colV = 5120 + h * 64;

#pragma unroll
  for (int i = 0; i < 2; i++) {
    int id = tid + i * 256;
    int r = id >> 4, c4 = (id & 15) * 4;
    int t = mv_token(bb, qt * 32 + r, ij, IS_COL);
    *(float4*)&Qs[r][c4] = *(const float4*)&g_QKV[(size_t)t * QKVN + colQ + c4];
  }
  const int q = tid >> 3;
  const int l8 = tid & 7;
  float m = -1e30f, lsum = 0.f;
  float o[8];
#pragma unroll
  for (int j = 0; j < 8; j++) o[j] = 0.f;

  for (int kt = 0; kt < 2; kt++) {
    __syncthreads();
#pragma unroll
    for (int i = 0; i < 4; i++) {
      int id = tid + i * 256;
      int r = id >> 4, c4 = (id & 15) * 4;
      int t = mv_token(bb, kt * 64 + r, ij, IS_COL);
      *(float4*)&KVs[r][c4] = *(const float4*)&g_QKV[(size_t)t * QKVN + colK + c4];
    }
    __syncthreads();
    float s[8];
#pragma unroll
    for (int j = 0; j < 8; j++) s[j] = 0.f;
#pragma unroll
    for (int d0 = 0; d0 < 64; d0 += 4) {
      float4 qv = *(const float4*)&Qs[q][d0];
#pragma unroll
      for (int j = 0; j < 8; j++) {
        float4 kv = *(const float4*)&KVs[j * 8 + l8][d0];
        s[j] += qv.x * kv.x + qv.y * kv.y + qv.z * kv.z + qv.w * kv.w;
      }
    }
    float tmax = -1e30f;
#pragma unroll
    for (int j = 0; j < 8; j++) { s[j] *= 0.125f; tmax = fmaxf(tmax, s[j]); }
#pragma unroll
    for (int off = 1; off < 8; off <<= 1)
      tmax = fmaxf(tmax, __shfl_xor_sync(0xffffffffu, tmax, off));
    float mnew = fmaxf(m, tmax);
    float corr = __expf(m - mnew);
    float psum = 0.f;
#pragma unroll
    for (int j = 0; j < 8; j++) {
      float p = __expf(s[j] - mnew);
      Ps[q][j * 8 + l8] = p;
      psum += p;
    }
#pragma unroll
    for (int off = 1; off < 8; off <<= 1)
      psum += __shfl_xor_sync(0xffffffffu, psum, off);
    lsum = lsum * corr + psum;
    m = mnew;
#pragma unroll
    for (int j = 0; j < 8; j++) o[j] *= corr;
    __syncthreads();
#pragma unroll
    for (int i = 0; i < 4; i++) {
      int id = tid + i * 256;
      int r = id >> 4, c4 = (id & 15) * 4;
      int t = mv_token(bb, kt * 64 + r, ij, IS_COL);
      *(float4*)&KVs[r][c4] = *(const float4*)&g_QKV[(size_t)t * QKVN + colV + c4];
    }
    __syncthreads();
#pragma unroll
    for (int k = 0; k < 64; k++) {
      float p = Ps[q][k];
      float4 v0 = *(const float4*)&KVs[k][l8 * 8];
      float4 v1 = *(const float4*)&KVs[k][l8 * 8 + 4];
      o[0] += p * v0.x; o[1] += p * v0.y; o[2] += p * v0.z; o[3] += p * v0.w;
      o[4] += p * v1.x; o[5] += p * v1.y; o[6] += p * v1.z; o[7] += p * v1.w;
    }
  }
  float inv = 1.f / lsum;
  const int t = mv_token(bb, qt * 32 + q, ij, IS_COL);
  float* dst = &g_ATT[(size_t)t * ATTN + 1024 + h * 64 + l8 * 8];
  float4 r0 = make_float4(o[0] * inv, o[1] * inv, o[2] * inv, o[3] * inv);
  float4 r1 = make_float4(o[4] * inv, o[5] * inv, o[6] * inv, o[7] * inv);
  if (IS_COL) {
    float w = (qt < 2) ? 0.5f : 1.0f;
    *(float4*)&dst[0] = make_float4(w * r0.x, w * r0.y, w * r0.z, w * r0.w);
    *(float4*)&dst[4] = make_float4(w * r1.x, w * r1.y, w * r1.z, w * r1.w);
  } else {
    if (qt == 0 || qt == 2) {
      float4 c0 = *(const float4*)&dst[0];
      float4 c1 = *(const float4*)&dst[4];
      c0.x += 0.5f * r0.x; c0.y += 0.5f * r0.y; c0.z += 0.5f * r0.z; c0.w += 0.5f * r0.w;
      c1.x += 0.5f * r1.x; c1.y += 0.5f * r1.y; c1.z += 0.5f * r1.z; c1.w += 0.5f * r1.w;
      *(float4*)&dst[0] = c0;
      *(float4*)&dst[4] = c1;
    } else {
      *(float4*)&dst[0] = r0;
      *(float4*)&dst[4] = r1;
    }
  }
}

// ---------------------------------------------------------------------------
extern "C" void kernel_launch(void* const* d_in, const int* in_sizes, int n_in,
                              void* d_out, int out_size) {
  (void)in_sizes; (void)n_in; (void)out_size;
  const float* x   = (const float*)d_in[0];
  const float* Wq  = (const float*)d_in[1];
  const float* Wk  = (const float*)d_in[2];
  const float* Wv  = (const float*)d_in[3];
  const float* Wo  = (const float*)d_in[4];
  const float* bo  = (const float*)d_in[5];
  const float* Wqm = (const float*)d_in[6];
  const float* Wkm = (const float*)d_in[7];
  const float* Wvm = (const float*)d_in[8];
  const float* Wom = (const float*)d_in[9];
  const float* bom = (const float*)d_in[10];
  float* out = (float*)d_out;

  Ptr6 B1;
  B1.p[0] = Wq;  B1.p[1] = Wk;  B1.p[2] = Wv;
  B1.p[3] = Wqm; B1.p[4] = Wkm; B1.p[5] = Wvm;

  gemm_qkv<<<dim3(QKVN / 128, TOK / 128), 256>>>(x, B1);
  attn_main<<<dim3(32, 192), 256>>>();
  attn_mv<1><<<dim3(4, 1024), 256>>>();   // col views: write
  attn_mv<0><<<dim3(4, 1024), 256>>>();   // row views: add/write (after col)
  gemm_out<<<dim3(DMODEL / 128, TOK / 128), 256>>>(Wo, Wom, bo, bom, x, out);
}

// round 3
// speedup vs baseline: 9.2146x; 6.3554x over previous
#include <cuda_runtime.h>
#include <cuda_bf16.h>
#include <cstdint>
#include <cstddef>

#define TOK    12288
#define DMODEL 1024
#define QKVN   6144
#define ATTN   2048

// Scratch (bf16 now): static device globals per harness rules
static __device__ __nv_bfloat16 g_QKV[(size_t)TOK * QKVN];  // [t][mat*1024+h*64+d]
static __device__ __nv_bfloat16 g_ATT[(size_t)TOK * ATTN];  // [t][0:1024)=main, [1024:2048)=mv

struct Ptr6 { const float* p[6]; };

// ---------------------------------------------------------------------------
// helpers
// ---------------------------------------------------------------------------
__device__ __forceinline__ unsigned pack_bf2(float lo, float hi) {
  unsigned d;
  asm("cvt.rn.bf16x2.f32 %0, %1, %2;" : "=r"(d) : "f"(hi), "f"(lo));  // first src -> high
  return d;
}
__device__ __forceinline__ unsigned smem_u32(const void* p) {
  return (unsigned)__cvta_generic_to_shared(p);
}
__device__ __forceinline__ void ldm_x4(unsigned* r, unsigned addr) {
  asm volatile("ldmatrix.sync.aligned.m8n8.x4.shared.b16 {%0,%1,%2,%3}, [%4];"
               : "=r"(r[0]), "=r"(r[1]), "=r"(r[2]), "=r"(r[3]) : "r"(addr));
}
__device__ __forceinline__ void ldm_x4t(unsigned* r, unsigned addr) {
  asm volatile("ldmatrix.sync.aligned.m8n8.x4.trans.shared.b16 {%0,%1,%2,%3}, [%4];"
               : "=r"(r[0]), "=r"(r[1]), "=r"(r[2]), "=r"(r[3]) : "r"(addr));
}
__device__ __forceinline__ void mma_bf16(float* d, const unsigned* a,
                                         const unsigned* b, const float* c) {
  asm volatile(
      "mma.sync.aligned.m16n8k16.row.col.f32.bf16.bf16.f32 "
      "{%0,%1,%2,%3}, {%4,%5,%6,%7}, {%8,%9}, {%10,%11,%12,%13};"
      : "=f"(d[0]), "=f"(d[1]), "=f"(d[2]), "=f"(d[3])
      : "r"(a[0]), "r"(a[1]), "r"(a[2]), "r"(a[3]), "r"(b[0]), "r"(b[1]),
        "f"(c[0]), "f"(c[1]), "f"(c[2]), "f"(c[3]));
}

// ---------------------------------------------------------------------------
// GEMM1 (bf16 mma): g_QKV[t,n] = sum_d x[t,d] * W_{n/1024}[n%1024, d]
// 128x128 tile, BK=32, 256 threads (8 warps, warp tile 64x32), double buffer.
// smem pitch 40 bf16 (80B) -> conflict-free ldmatrix.
// ---------------------------------------------------------------------------
#define BPITCH 40
__global__ __launch_bounds__(256) void gemm_qkv(const float* __restrict__ A, Ptr6 B) {
  __shared__ __align__(16) __nv_bfloat16 As[2][128 * BPITCH];
  __shared__ __align__(16) __nv_bfloat16 Bs[2][128 * BPITCH];
  const int tid = threadIdx.x;
  const int m0 = blockIdx.y * 128, n0 = blockIdx.x * 128;
  const float* __restrict__ Bmat = B.p[n0 >> 10];
  const int br0 = n0 & 1023;
  const int lane = tid & 31, wid = tid >> 5;
  const int wm = (wid & 1) * 64, wn = (wid >> 1) * 32;
  const int g = lane >> 2, tg = lane & 3;
  const int brow = tid >> 3, c4 = (tid & 7) * 4;

  float acc[4][4][4];
#pragma unroll
  for (int mi = 0; mi < 4; mi++)
#pragma unroll
    for (int ni = 0; ni < 4; ni++)
#pragma unroll
      for (int r = 0; r < 4; r++) acc[mi][ni][r] = 0.f;

  float4 av[4], bv[4];
#pragma unroll
  for (int i = 0; i < 4; i++) {
    av[i] = *(const float4*)&A[(size_t)(m0 + brow + 32 * i) * DMODEL + c4];
    bv[i] = *(const float4*)&Bmat[(size_t)(br0 + brow + 32 * i) * DMODEL + c4];
  }
#pragma unroll
  for (int i = 0; i < 4; i++) {
    uint2 ua = make_uint2(pack_bf2(av[i].x, av[i].y), pack_bf2(av[i].z, av[i].w));
    uint2 ub = make_uint2(pack_bf2(bv[i].x, bv[i].y), pack_bf2(bv[i].z, bv[i].w));
    *(uint2*)&As[0][(brow + 32 * i) * BPITCH + c4] = ua;
    *(uint2*)&Bs[0][(brow + 32 * i) * BPITCH + c4] = ub;
  }
  __syncthreads();

  const int NC = DMODEL / 32;
  for (int kc = 0; kc < NC; kc++) {
    const int buf = kc & 1;
    if (kc + 1 < NC) {
      const int k0 = (kc + 1) * 32;
#pragma unroll
      for (int i = 0; i < 4; i++) {
        av[i] = *(const float4*)&A[(size_t)(m0 + brow + 32 * i) * DMODEL + k0 + c4];
        bv[i] = *(const float4*)&Bmat[(size_t)(br0 + brow + 32 * i) * DMODEL + k0 + c4];
      }
    }
    const unsigned asmb = smem_u32(&As[buf][0]);
    const unsigned bsmb = smem_u32(&Bs[buf][0]);
#pragma unroll
    for (int ks = 0; ks < 2; ks++) {
      const int kk = ks * 16;
      unsigned afr[4][4];
#pragma unroll
      for (int mi = 0; mi < 4; mi++)
        ldm_x4(afr[mi], asmb + ((wm + mi * 16 + (lane & 15)) * BPITCH + kk + (lane >> 4) * 8) * 2);
#pragma unroll
      for (int n2 = 0; n2 < 2; n2++) {
        unsigned bfr[4];
        ldm_x4(bfr, bsmb + ((wn + n2 * 16 + (lane >> 4) * 8 + (lane & 7)) * BPITCH +
                            kk + ((lane >> 3) & 1) * 8) * 2);
#pragma unroll
        for (int mi = 0; mi < 4; mi++) {
          mma_bf16(acc[mi][2 * n2], afr[mi], bfr, acc[mi][2 * n2]);
          mma_bf16(acc[mi][2 * n2 + 1], afr[mi], bfr + 2, acc[mi][2 * n2 + 1]);
        }
      }
    }
    if (kc + 1 < NC) {
      const int nb = buf ^ 1;
#pragma unroll
      for (int i = 0; i < 4; i++) {
        uint2 ua = make_uint2(pack_bf2(av[i].x, av[i].y), pack_bf2(av[i].z, av[i].w));
        uint2 ub = make_uint2(pack_bf2(bv[i].x, bv[i].y), pack_bf2(bv[i].z, bv[i].w));
        *(uint2*)&As[nb][(brow + 32 * i) * BPITCH + c4] = ua;
        *(uint2*)&Bs[nb][(brow + 32 * i) * BPITCH + c4] = ub;
      }
      __syncthreads();
    }
  }
#pragma unroll
  for (int mi = 0; mi < 4; mi++)
#pragma unroll
    for (int ni = 0; ni < 4; ni++) {
      const int row = m0 + wm + mi * 16 + g;
      const int col = n0 + wn + ni * 8 + 2 * tg;
      *(unsigned*)&g_QKV[(size_t)row * QKVN + col] =
          pack_bf2(acc[mi][ni][0], acc[mi][ni][1]);
      *(unsigned*)&g_QKV[(size_t)(row + 8) * QKVN + col] =
          pack_bf2(acc[mi][ni][2], acc[mi][ni][3]);
    }
}

// ---------------------------------------------------------------------------
// GEMM2 (bf16 mma): out = [ATT_main|ATT_mv] @ [Wo|Wom]^T + bo + bom + x
// ---------------------------------------------------------------------------
__global__ __launch_bounds__(256) void gemm_out(
    const float* __restrict__ Wo, const float* __restrict__ Wom,
    const float* __restrict__ bo, const float* __restrict__ bom,
    const float* __restrict__ X, float* __restrict__ Out) {
  __shared__ __align__(16) __nv_bfloat16 As[2][128 * BPITCH];
  __shared__ __align__(16) __nv_bfloat16 Bs[2][128 * BPITCH];
  const int tid = threadIdx.x;
  const int m0 = blockIdx.y * 128, n0 = blockIdx.x * 128;
  const int lane = tid & 31, wid = tid >> 5;
  const int wm = (wid & 1) * 64, wn = (wid >> 1) * 32;
  const int g = lane >> 2, tg = lane & 3;
  const int brow = tid >> 3, c4 = (tid & 7) * 4;

  float acc[4][4][4];
#pragma unroll
  for (int mi = 0; mi < 4; mi++)
#pragma unroll
    for (int ni = 0; ni < 4; ni++)
#pragma unroll
      for (int r = 0; r < 4; r++) acc[mi][ni][r] = 0.f;

  uint2 av[4];
  float4 bv[4];
#pragma unroll
  for (int i = 0; i < 4; i++) {
    av[i] = *(const uint2*)&g_ATT[(size_t)(m0 + brow + 32 * i) * ATTN + c4];
    bv[i] = *(const float4*)&Wo[(size_t)(n0 + brow + 32 * i) * DMODEL + c4];
  }
#pragma unroll
  for (int i = 0; i < 4; i++) {
    *(uint2*)&As[0][(brow + 32 * i) * BPITCH + c4] = av[i];
    *(uint2*)&Bs[0][(brow + 32 * i) * BPITCH + c4] =
        make_uint2(pack_bf2(bv[i].x, bv[i].y), pack_bf2(bv[i].z, bv[i].w));
  }
  __syncthreads();

  const int NC = ATTN / 32;
  for (int kc = 0; kc < NC; kc++) {
    const int buf = kc & 1;
    if (kc + 1 < NC) {
      const int k0 = (kc + 1) * 32;
      const float* __restrict__ Bm = (k0 < 1024) ? Wo : Wom;
      const int kcc = k0 & 1023;
#pragma unroll
      for (int i = 0; i < 4; i++) {
        av[i] = *(const uint2*)&g_ATT[(size_t)(m0 + brow + 32 * i) * ATTN + k0 + c4];
        bv[i] = *(const float4*)&Bm[(size_t)(n0 + brow + 32 * i) * DMODEL + kcc + c4];
      }
    }
    const unsigned asmb = smem_u32(&As[buf][0]);
    const unsigned bsmb = smem_u32(&Bs[buf][0]);
#pragma unroll
    for (int ks = 0; ks < 2; ks++) {
      const int kk = ks * 16;
      unsigned afr[4][4];
#pragma unroll
      for (int mi = 0; mi < 4; mi++)
        ldm_x4(afr[mi], asmb + ((wm + mi * 16 + (lane & 15)) * BPITCH + kk + (lane >> 4) * 8) * 2);
#pragma unroll
      for (int n2 = 0; n2 < 2; n2++) {
        unsigned bfr[4];
        ldm_x4(bfr, bsmb + ((wn + n2 * 16 + (lane >> 4) * 8 + (lane & 7)) * BPITCH +
                            kk + ((lane >> 3) & 1) * 8) * 2);
#pragma unroll
        for (int mi = 0; mi < 4; mi++) {
          mma_bf16(acc[mi][2 * n2], afr[mi], bfr, acc[mi][2 * n2]);
          mma_bf16(acc[mi][2 * n2 + 1], afr[mi], bfr + 2, acc[mi][2 * n2 + 1]);
        }
      }
    }
    if (kc + 1 < NC) {
      const int nb = buf ^ 1;
#pragma unroll
      for (int i = 0; i < 4; i++) {
        *(uint2*)&As[nb][(brow + 32 * i) * BPITCH + c4] = av[i];
        *(uint2*)&Bs[nb][(brow + 32 * i) * BPITCH + c4] =
            make_uint2(pack_bf2(bv[i].x, bv[i].y), pack_bf2(bv[i].z, bv[i].w));
      }
      __syncthreads();
    }
  }
#pragma unroll
  for (int mi = 0; mi < 4; mi++)
#pragma unroll
    for (int ni = 0; ni < 4; ni++) {
      const int row = m0 + wm + mi * 16 + g;
      const int col = n0 + wn + ni * 8 + 2 * tg;
      const float bias0 = bo[col] + bom[col];
      const float bias1 = bo[col + 1] + bom[col + 1];
      float2 x0 = *(const float2*)&X[(size_t)row * DMODEL + col];
      float2 x1 = *(const float2*)&X[(size_t)(row + 8) * DMODEL + col];
      *(float2*)&Out[(size_t)row * DMODEL + col] =
          make_float2(acc[mi][ni][0] + bias0 + x0.x, acc[mi][ni][1] + bias1 + x0.y);
      *(float2*)&Out[(size_t)(row + 8) * DMODEL + col] =
          make_float2(acc[mi][ni][2] + bias0 + x1.x, acc[mi][ni][3] + bias1 + x1.y);
    }
}

// ---------------------------------------------------------------------------
// Flash attention core on mma.sync (shared by main and mv kernels).
// Block = 128 threads (4 warps), Q tile 64 rows, key tiles of 64, Dh=64.
// ---------------------------------------------------------------------------
#define APITCH 72

// one key-tile step: S=Q K^T, online softmax, O += P V
__device__ __forceinline__ void fa_tile(
    unsigned qsm, unsigned ksm, unsigned vsm, int lane, int wrow,
    float& m0v, float& m1v, float& l0, float& l1, float o[8][4]) {
  const int half = (lane >> 3) & 1, quad = lane >> 4;
  float s[8][4];
#pragma unroll
  for (int nf = 0; nf < 8; nf++)
#pragma unroll
    for (int r = 0; r < 4; r++) s[nf][r] = 0.f;
#pragma unroll
  for (int kcc = 0; kcc < 4; kcc++) {
    unsigned a[4];
    ldm_x4(a, qsm + ((wrow + (lane & 15)) * APITCH + kcc * 16 + quad * 8) * 2);
#pragma unroll
    for (int n2 = 0; n2 < 4; n2++) {
      unsigned bf[4];
      ldm_x4(bf, ksm + ((n2 * 16 + quad * 8 + (lane & 7)) * APITCH + kcc * 16 + half * 8) * 2);
      mma_bf16(s[2 * n2], a, bf, s[2 * n2]);
      mma_bf16(s[2 * n2 + 1], a, bf + 2, s[2 * n2 + 1]);
    }
  }
  float mx0 = -1e30f, mx1 = -1e30f;
#pragma unroll
  for (int nf = 0; nf < 8; nf++) {
#pragma unroll
    for (int r = 0; r < 4; r++) s[nf][r] *= 0.125f;
    mx0 = fmaxf(mx0, fmaxf(s[nf][0], s[nf][1]));
    mx1 = fmaxf(mx1, fmaxf(s[nf][2], s[nf][3]));
  }
  mx0 = fmaxf(mx0, __shfl_xor_sync(0xffffffffu, mx0, 1));
  mx0 = fmaxf(mx0, __shfl_xor_sync(0xffffffffu, mx0, 2));
  mx1 = fmaxf(mx1, __shfl_xor_sync(0xffffffffu, mx1, 1));
  mx1 = fmaxf(mx1, __shfl_xor_sync(0xffffffffu, mx1, 2));
  const float nm0 = fmaxf(m0v, mx0), nm1 = fmaxf(m1v, mx1);
  const float c0 = __expf(m0v - nm0), c1 = __expf(m1v - nm1);
  m0v = nm0; m1v = nm1;
  float sum0 = 0.f, sum1 = 0.f;
  unsigned pa[4][4];
#pragma unroll
  for (int j = 0; j < 4; j++) {
    float p00 = __expf(s[2 * j][0] - nm0), p01 = __expf(s[2 * j][1] - nm0);
    float p02 = __expf(s[2 * j][2] - nm1), p03 = __expf(s[2 * j][3] - nm1);
    float p10 = __expf(s[2 * j + 1][0] - nm0), p11 = __expf(s[2 * j + 1][1] - nm0);
    float p12 = __expf(s[2 * j + 1][2] - nm1), p13 = __expf(s[2 * j + 1][3] - nm1);
    pa[j][0] = pack_bf2(p00, p01);
    pa[j][1] = pack_bf2(p02, p03);
    pa[j][2] = pack_bf2(p10, p11);
    pa[j][3] = pack_bf2(p12, p13);
    sum0 += p00 + p01 + p10 + p11;
    sum1 += p02 + p03 + p12 + p13;
  }
  sum0 += __shfl_xor_sync(0xffffffffu, sum0, 1);
  sum0 += __shfl_xor_sync(0xffffffffu, sum0, 2);
  sum1 += __shfl_xor_sync(0xffffffffu, sum1, 1);
  sum1 += __shfl_xor_sync(0xffffffffu, sum1, 2);
  l0 = l0 * c0 + sum0;
  l1 = l1 * c1 + sum1;
#pragma unroll
  for (int df = 0; df < 8; df++) {
    o[df][0] *= c0; o[df][1] *= c0; o[df][2] *= c1; o[df][3] *= c1;
  }
#pragma unroll
  for (int j = 0; j < 4; j++)
#pragma unroll
    for (int d2 = 0; d2 < 4; d2++) {
      unsigned bf[4];
      ldm_x4t(bf, vsm + ((j * 16 + half * 8 + (lane & 7)) * APITCH + d2 * 16 + quad * 8) * 2);
      mma_bf16(o[2 * d2], pa[j], bf, o[2 * d2]);
      mma_bf16(o[2 * d2 + 1], pa[j], bf + 2, o[2 * d2 + 1]);
    }
}

// ---------------------------------------------------------------------------
// Main attention: grid (16 qtiles, 192 bh).
// ---------------------------------------------------------------------------
__global__ __launch_bounds__(128) void attn_main() {
  __shared__ __align__(16) __nv_bfloat16 Qs[64 * APITCH];
  __shared__ __align__(16) __nv_bfloat16 Ks[64 * APITCH];
  __shared__ __align__(16) __nv_bfloat16 Vs[64 * APITCH];
  const int tid = threadIdx.x, lane = tid & 31, w = tid >> 5;
  const int qt = blockIdx.x;
  const int b = blockIdx.y >> 4, h = blockIdx.y & 15;
  const int tb = b << 10;
  const int colQ = h * 64, colK = 1024 + h * 64, colV = 2048 + h * 64;

#pragma unroll
  for (int i = 0; i < 4; i++) {
    int u = tid + i * 128;
    int r = u >> 3, o8 = (u & 7) * 8;
    *(uint4*)&Qs[r * APITCH + o8] =
        *(const uint4*)&g_QKV[(size_t)(tb + qt * 64 + r) * QKVN + colQ + o8];
  }
  const int g = lane >> 2, tg = lane & 3;
  const int wrow = w * 16;
  float m0v = -1e30f, m1v = -1e30f, l0 = 0.f, l1 = 0.f;
  float o[8][4];
#pragma unroll
  for (int df = 0; df < 8; df++)
#pragma unroll
    for (int r = 0; r < 4; r++) o[df][r] = 0.f;
  const unsigned qsm = smem_u32(Qs), ksm = smem_u32(Ks), vsm = smem_u32(Vs);

  for (int kt = 0; kt < 16; kt++) {
    __syncthreads();
#pragma unroll
    for (int i = 0; i < 4; i++) {
      int u = tid + i * 128;
      int r = u >> 3, o8 = (u & 7) * 8;
      size_t trow = (size_t)(tb + kt * 64 + r) * QKVN;
      *(uint4*)&Ks[r * APITCH + o8] = *(const uint4*)&g_QKV[trow + colK + o8];
      *(uint4*)&Vs[r * APITCH + o8] = *(const uint4*)&g_QKV[trow + colV + o8];
    }
    __syncthreads();
    fa_tile(qsm, ksm, vsm, lane, wrow, m0v, m1v, l0, l1, o);
  }
  const float i0 = 1.f / l0, i1 = 1.f / l1;
  const int row = tb + qt * 64 + wrow + g;
#pragma unroll
  for (int df = 0; df < 8; df++) {
    const int col = h * 64 + df * 8 + 2 * tg;
    *(unsigned*)&g_ATT[(size_t)row * ATTN + col] = pack_bf2(o[df][0] * i0, o[df][1] * i0);
    *(unsigned*)&g_ATT[(size_t)(row + 8) * ATTN + col] = pack_bf2(o[df][2] * i1, o[df][3] * i1);
  }
}

// ---------------------------------------------------------------------------
// Row/Col view attention: grid (2 qtiles, 1024 groups). Seq=128 (2 key tiles).
// ---------------------------------------------------------------------------
__device__ __forceinline__ int mv_token(int bb, int j, int ij, int is_col) {
  int c = j >> 5, pos = j & 31;
  int nv = is_col ? ((c < 3) ? 2 * c : 5) : c;  // COL_IDX = {0,2,4,5}
  int s  = is_col ? (pos * 32 + ij) : (ij * 32 + pos);
  return (bb * 6 + nv) * 1024 + s;
}

template <int IS_COL>
__global__ __launch_bounds__(128) void attn_mv() {
  __shared__ __align__(16) __nv_bfloat16 Qs[64 * APITCH];
  __shared__ __align__(16) __nv_bfloat16 Ks[64 * APITCH];
  __shared__ __align__(16) __nv_bfloat16 Vs[64 * APITCH];
  const int tid = threadIdx.x, lane = tid & 31, w = tid >> 5;
  const int qt = blockIdx.x;               // 0..1
  const int gy = blockIdx.y;
  const int h = gy & 15;
  const int ij = (gy >> 4) & 31;
  const int bb = gy >> 9;
  const int colQ = 3072 + h * 64, colK = 4096 + h * 64, colV = 5120 + h * 64;

#pragma unroll
  for (int i = 0; i < 4; i++) {
    int u = tid + i * 128;
    int r = u >> 3, o8 = (u & 7) * 8;
    int t = mv_token(bb, qt * 64 + r, ij, IS_COL);
    *(uint4*)&Qs[r * APITCH + o8] = *(const uint4*)&g_QKV[(size_t)t * QKVN + colQ + o8];
  }
  const int g = lane >> 2, tg = lane & 3;
  const int wrow = w * 16;
  float m0v = -1e30f, m1v = -1e30f, l0 = 0.f, l1 = 0.f;
  float o[8][4];
#pragma unroll
  for (int df = 0; df < 8; df++)
#pragma unroll
    for (int r = 0; r < 4; r++) o[df][r] = 0.f;
  const unsigned qsm = smem_u32(Qs), ksm = smem_u32(Ks), vsm = smem_u32(Vs);

  for (int kt = 0; kt < 2; kt++) {
    __syncthreads();
#pragma unroll
    for (int i = 0; i < 4; i++) {
      int u = tid + i * 128;
      int r = u >> 3, o8 = (u & 7) * 8;
      size_t trow = (size_t)mv_token(bb, kt * 64 + r, ij, IS_COL) * QKVN;
      *(uint4*)&Ks[r * APITCH + o8] = *(const uint4*)&g_QKV[trow + colK + o8];
      *(uint4*)&Vs[r * APITCH + o8] = *(const uint4*)&g_QKV[trow + colV + o8];
    }
    __syncthreads();
    fa_tile(qsm, ksm, vsm, lane, wrow, m0v, m1v, l0, l1, o);
  }
  const float i0 = 1.f / l0, i1 = 1.f / l1;
  const int t0 = mv_token(bb, qt * 64 + wrow + g, ij, IS_COL);
  const int t1 = mv_token(bb, qt * 64 + wrow + g + 8, ij, IS_COL);
  const int half16 = w >> 1;  // 0: rows <32 of this qtile, 1: rows >=32
#pragma unroll
  for (int df = 0; df < 8; df++) {
    const int col = 1024 + h * 64 + df * 8 + 2 * tg;
    float v00 = o[df][0] * i0, v01 = o[df][1] * i0;
    float v10 = o[df][2] * i1, v11 = o[df][3] * i1;
    unsigned* d0 = (unsigned*)&g_ATT[(size_t)t0 * ATTN + col];
    unsigned* d1 = (unsigned*)&g_ATT[(size_t)t1 * ATTN + col];
    if (IS_COL) {
      // col runs first: always WRITE; weight 0.5 for c in {0,1} (qt==0)
      const float wgt = (qt == 0) ? 0.5f : 1.0f;
      *d0 = pack_bf2(v00 * wgt, v01 * wgt);
      *d1 = pack_bf2(v10 * wgt, v11 * wgt);
    } else {
      // row runs second: nv = 2*qt + half16; ADD 0.5x if nv even, else WRITE
      if (half16 == 0) {
        float2 p0 = __bfloat1622float2(*(__nv_bfloat162*)d0);
        float2 p1 = __bfloat1622float2(*(__nv_bfloat162*)d1);
        *d0 = pack_bf2(p0.x + 0.5f * v00, p0.y + 0.5f * v01);
        *d1 = pack_bf2(p1.x + 0.5f * v10, p1.y + 0.5f * v11);
      } else {
        *d0 = pack_bf2(v00, v01);
        *d1 = pack_bf2(v10, v11);
      }
    }
  }
}

// ---------------------------------------------------------------------------
extern "C" void kernel_launch(void* const* d_in, const int* in_sizes, int n_in,
                              void* d_out, int out_size) {
  (void)in_sizes; (void)n_in; (void)out_size;
  const float* x   = (const float*)d_in[0];
  const float* Wq  = (const float*)d_in[1];
  const float* Wk  = (const float*)d_in[2];
  const float* Wv  = (const float*)d_in[3];
  const float* Wo  = (const float*)d_in[4];
  const float* bo  = (const float*)d_in[5];
  const float* Wqm = (const float*)d_in[6];
  const float* Wkm = (const float*)d_in[7];
  const float* Wvm = (const float*)d_in[8];
  const float* Wom = (const float*)d_in[9];
  const float* bom = (const float*)d_in[10];
  float* out = (float*)d_out;

  Ptr6 B1;
  B1.p[0] = Wq;  B1.p[1] = Wk;  B1.p[2] = Wv;
  B1.p[3] = Wqm; B1.p[4] = Wkm; B1.p[5] = Wvm;

  gemm_qkv<<<dim3(QKVN / 128, TOK / 128), 256>>>(x, B1);
  attn_main<<<dim3(16, 192), 128>>>();
  attn_mv<1><<<dim3(2, 1024), 128>>>();   // col views: write
  attn_mv<0><<<dim3(2, 1024), 128>>>();   // row views: add/write (after col)
  gemm_out<<<dim3(DMODEL / 128, TOK / 128), 256>>>(Wo, Wom, bo, bom, x, out);
}